// round 15
// baseline (speedup 1.0000x reference)
#include <cuda_runtime.h>
#include <math.h>

// ---------------- problem constants ----------------
#define Dm   1024
#define Hh   8
#define HDm  128
#define FFm  1024
#define ESn  2048
#define NNn  1024
#define EPn  16384
#define Kn   4096
#define LNEPS 1e-5f

// ---------------- scratch (static device globals; no allocation) ----------------
// layout in floats (M1 = 1M floats):
//  Q:0(2M) K:2(4M) V:6(4M) S:10(64M) O:74(2M) T1:76(2M) ACC:78(2M)
//  SP:80(2M) SU:82(1M) E2E:83(4M) N2E:87(4M) UPB:91(2M) UUB:93(1M) HID:94(2M)  total 96M
#define M1 1048576LL
__device__ float g_scratch[96 * 1048576];
__device__ int   g_pos[EPn];

// ---------------- block reductions ----------------
__device__ __forceinline__ float blockReduceSum(float v) {
    __shared__ float sh[32];
    __shared__ float tot;
    int lane = threadIdx.x & 31, wid = threadIdx.x >> 5;
    #pragma unroll
    for (int o = 16; o > 0; o >>= 1) v += __shfl_down_sync(0xffffffffu, v, o);
    if (lane == 0) sh[wid] = v;
    __syncthreads();
    v = (threadIdx.x < (blockDim.x >> 5)) ? sh[threadIdx.x] : 0.f;
    if (wid == 0) {
        #pragma unroll
        for (int o = 16; o > 0; o >>= 1) v += __shfl_down_sync(0xffffffffu, v, o);
        if (lane == 0) tot = v;
    }
    __syncthreads();
    return tot;
}

__device__ __forceinline__ float blockReduceMax(float v) {
    __shared__ float sh[32];
    __shared__ float tot;
    int lane = threadIdx.x & 31, wid = threadIdx.x >> 5;
    #pragma unroll
    for (int o = 16; o > 0; o >>= 1) v = fmaxf(v, __shfl_down_sync(0xffffffffu, v, o));
    if (lane == 0) sh[wid] = v;
    __syncthreads();
    v = (threadIdx.x < (blockDim.x >> 5)) ? sh[threadIdx.x] : -1e30f;
    if (wid == 0) {
        #pragma unroll
        for (int o = 16; o > 0; o >>= 1) v = fmaxf(v, __shfl_down_sync(0xffffffffu, v, o));
        if (lane == 0) tot = v;
    }
    __syncthreads();
    return tot;
}

// ---------------- generic batched tiled SGEMM ----------------
// C[M,N] = alpha * A(M,Kd) x op(B) (+ bias[n]) (+ C) (ReLU)
// TRANSB=true : B is [N,Kd] row-major (dot of rows)   -> X @ W^T
// TRANSB=false: B is [Kd,N] row-major                  -> S @ V
template<int BM, int BN, int TM, int TN, bool TRANSB, bool ADDC, bool RELU>
__global__ void __launch_bounds__(256)
gemm_kernel(const float* __restrict__ A, const float* __restrict__ B,
            float* __restrict__ C, const float* __restrict__ bias,
            int M, int N, int Kd, int lda, int ldb, int ldc,
            long sA, long sB, long sC, float alpha)
{
    constexpr int BK = 16;
    __shared__ float As[BK][BM];
    __shared__ float Bs[BK][BN];
    A += (long)blockIdx.z * sA;
    B += (long)blockIdx.z * sB;
    C += (long)blockIdx.z * sC;
    const int bm = blockIdx.y * BM;
    const int bn = blockIdx.x * BN;
    const int tid = threadIdx.x;
    constexpr int TCOLS = BN / TN;
    const int tx = tid % TCOLS;
    const int ty = tid / TCOLS;

    float acc[TM][TN];
    #pragma unroll
    for (int i = 0; i < TM; i++)
        #pragma unroll
        for (int j = 0; j < TN; j++) acc[i][j] = 0.f;

    for (int k0 = 0; k0 < Kd; k0 += BK) {
        // A tile -> As[k][m] (transposed on load)
        constexpr int LA = (BM * BK / 4) / 256;
        #pragma unroll
        for (int i = 0; i < LA; i++) {
            int idx = tid + i * 256;
            int row = idx >> 2;            // BK/4 = 4 float4 per row
            int c   = (idx & 3) << 2;
            const float4 v = *(const float4*)(A + (long)(bm + row) * lda + k0 + c);
            As[c + 0][row] = v.x; As[c + 1][row] = v.y;
            As[c + 2][row] = v.z; As[c + 3][row] = v.w;
        }
        if (TRANSB) {
            constexpr int LB = (BN * BK / 4) / 256;
            #pragma unroll
            for (int i = 0; i < LB; i++) {
                int idx = tid + i * 256;
                int row = idx >> 2;
                int c   = (idx & 3) << 2;
                const float4 v = *(const float4*)(B + (long)(bn + row) * ldb + k0 + c);
                Bs[c + 0][row] = v.x; Bs[c + 1][row] = v.y;
                Bs[c + 2][row] = v.z; Bs[c + 3][row] = v.w;
            }
        } else {
            constexpr int LB = (BK * BN / 4) / 256;
            constexpr int C4 = BN / 4;
            #pragma unroll
            for (int i = 0; i < LB; i++) {
                int idx = tid + i * 256;
                int kr  = idx / C4;
                int c   = (idx % C4) << 2;
                *(float4*)(&Bs[kr][c]) =
                    *(const float4*)(B + (long)(k0 + kr) * ldb + bn + c);
            }
        }
        __syncthreads();
        #pragma unroll
        for (int k = 0; k < BK; k++) {
            float af[TM], bf[TN];
            #pragma unroll
            for (int i = 0; i < TM; i += 4)
                *(float4*)(af + i) = *(const float4*)(&As[k][ty * TM + i]);
            #pragma unroll
            for (int j = 0; j < TN; j += 4)
                *(float4*)(bf + j) = *(const float4*)(&Bs[k][tx * TN + j]);
            #pragma unroll
            for (int i = 0; i < TM; i++)
                #pragma unroll
                for (int j = 0; j < TN; j++)
                    acc[i][j] = fmaf(af[i], bf[j], acc[i][j]);
        }
        __syncthreads();
    }

    #pragma unroll
    for (int i = 0; i < TM; i++) {
        const long m = bm + ty * TM + i;
        #pragma unroll
        for (int j = 0; j < TN; j += 4) {
            const int n = bn + tx * TN + j;
            float4 r;
            r.x = acc[i][j + 0] * alpha; r.y = acc[i][j + 1] * alpha;
            r.z = acc[i][j + 2] * alpha; r.w = acc[i][j + 3] * alpha;
            if (bias) {
                const float4 bb = *(const float4*)(bias + n);
                r.x += bb.x; r.y += bb.y; r.z += bb.z; r.w += bb.w;
            }
            if (ADDC) {
                const float4 c0 = *(const float4*)(C + m * ldc + n);
                r.x += c0.x; r.y += c0.y; r.z += c0.z; r.w += c0.w;
            }
            if (RELU) {
                r.x = fmaxf(r.x, 0.f); r.y = fmaxf(r.y, 0.f);
                r.z = fmaxf(r.z, 0.f); r.w = fmaxf(r.w, 0.f);
            }
            *(float4*)(C + m * ldc + n) = r;
        }
    }
}

// ---------------- softmax over last dim (one block per row) ----------------
__global__ void softmax_kernel(float* __restrict__ S, int Lk) {
    float* p = S + (long)blockIdx.x * Lk;
    const int tid = threadIdx.x;
    float m = -1e30f;
    for (int i = tid; i < Lk; i += 256) m = fmaxf(m, p[i]);
    m = blockReduceMax(m);
    float s = 0.f;
    for (int i = tid; i < Lk; i += 256) {
        float e = expf(p[i] - m);
        p[i] = e;
        s += e;
    }
    s = blockReduceSum(s);
    const float inv = 1.0f / s;
    for (int i = tid; i < Lk; i += 256) p[i] *= inv;
}

// ---------------- fused residual add + LayerNorm (one block per row) ----------------
__global__ void add_ln_kernel(const float* __restrict__ a, const float* __restrict__ b,
                              const float* __restrict__ g, const float* __restrict__ be,
                              float* __restrict__ out) {
    const int row = blockIdx.x;
    const int tid = threadIdx.x;
    const float* pa = a + (long)row * Dm;
    const float* pb = b + (long)row * Dm;
    float v[4];
    float s = 0.f;
    #pragma unroll
    for (int i = 0; i < 4; i++) {
        int c = tid + i * 256;
        v[i] = pa[c] + pb[c];
        s += v[i];
    }
    s = blockReduceSum(s);
    const float mu = s * (1.0f / Dm);
    float q = 0.f;
    #pragma unroll
    for (int i = 0; i < 4; i++) { float d = v[i] - mu; q += d * d; }
    q = blockReduceSum(q);
    const float rstd = rsqrtf(q * (1.0f / Dm) + LNEPS);
    #pragma unroll
    for (int i = 0; i < 4; i++) {
        int c = tid + i * 256;
        out[(long)row * Dm + c] = (v[i] - mu) * rstd * g[c] + be[c];
    }
}

// ---------------- scatter/gather plumbing ----------------
__global__ void init_pos_kernel(int* pos) {
    int i = blockIdx.x * 256 + threadIdx.x;
    pos[i] = -1;
}
__global__ void scatter_pos_kernel(const int* __restrict__ ind, int* pos) {
    int i = blockIdx.x * 256 + threadIdx.x;
    pos[ind[i]] = i;
}
// out[j,:] = pos[ind[j]]>=0 ? sp[pos] : entire_pair[ind[j]]
__global__ void gather_rows_kernel(const int* __restrict__ ind, const int* __restrict__ pos,
                                   const float* __restrict__ sp, const float* __restrict__ ep,
                                   float* __restrict__ out) {
    long t = (long)blockIdx.x * 256 + threadIdx.x; // one float4 per thread
    int j = (int)(t >> 8);                         // D/4 = 256 float4 per row
    int c = (int)(t & 255) << 2;
    int idx = ind[j];
    int p = pos[idx];
    const float* src = (p >= 0) ? (sp + (long)p * Dm) : (ep + (long)idx * Dm);
    *(float4*)(out + (long)j * Dm + c) = *(const float4*)(src + c);
}

// ---------------- host-side GEMM dispatch ----------------
template<bool TB, bool AC, bool RL>
static void gemm_t(const float* A, const float* B, float* C, const float* bias,
                   int M, int N, int Kd, int lda, int ldb, int ldc,
                   long sA, long sB, long sC, int batch, float alpha)
{
    bool big = (M % 128 == 0) && (N % 128 == 0) &&
               ((long)(M / 128) * (N / 128) * batch >= 160);
    if (big) {
        dim3 g(N / 128, M / 128, batch);
        gemm_kernel<128, 128, 8, 8, TB, AC, RL><<<g, 256>>>(
            A, B, C, bias, M, N, Kd, lda, ldb, ldc, sA, sB, sC, alpha);
    } else {
        dim3 g(N / 64, M / 64, batch);
        gemm_kernel<64, 64, 4, 4, TB, AC, RL><<<g, 256>>>(
            A, B, C, bias, M, N, Kd, lda, ldb, ldc, sA, sB, sC, alpha);
    }
}

static void gemm(bool transb, bool addc, bool relu,
                 const float* A, const float* B, float* C, const float* bias,
                 int M, int N, int Kd, int lda, int ldb, int ldc,
                 long sA, long sB, long sC, int batch, float alpha)
{
    if (transb) {
        if (addc) {
            if (relu) gemm_t<true, true, true>(A,B,C,bias,M,N,Kd,lda,ldb,ldc,sA,sB,sC,batch,alpha);
            else      gemm_t<true, true, false>(A,B,C,bias,M,N,Kd,lda,ldb,ldc,sA,sB,sC,batch,alpha);
        } else {
            if (relu) gemm_t<true, false, true>(A,B,C,bias,M,N,Kd,lda,ldb,ldc,sA,sB,sC,batch,alpha);
            else      gemm_t<true, false, false>(A,B,C,bias,M,N,Kd,lda,ldb,ldc,sA,sB,sC,batch,alpha);
        }
    } else {
        if (addc) {
            if (relu) gemm_t<false, true, true>(A,B,C,bias,M,N,Kd,lda,ldb,ldc,sA,sB,sC,batch,alpha);
            else      gemm_t<false, true, false>(A,B,C,bias,M,N,Kd,lda,ldb,ldc,sA,sB,sC,batch,alpha);
        } else {
            if (relu) gemm_t<false, false, true>(A,B,C,bias,M,N,Kd,lda,ldb,ldc,sA,sB,sC,batch,alpha);
            else      gemm_t<false, false, false>(A,B,C,bias,M,N,Kd,lda,ldb,ldc,sA,sB,sC,batch,alpha);
        }
    }
}

// ---------------- MHA driver ----------------
// outp[Lq, D] (+=) = MHA_i(q_in, kv_in)
static void run_mha(int i, const float* qin, int Lq, const float* kvin, int Lk,
                    float* outp, bool addc,
                    const float* Win, const float* bin,
                    const float* Wout, const float* bout,
                    float* Q, float* Kb, float* Vb, float* S, float* O)
{
    const float* W  = Win + (size_t)i * 3 * Dm * Dm;
    const float* b  = bin + (size_t)i * 3 * Dm;
    const float* Wo = Wout + (size_t)i * Dm * Dm;
    const float* bo = bout + (size_t)i * Dm;
    const float scale = 0.08838834764831845f;  // 1/sqrt(128)

    // projections: X @ W^T + b
    gemm(true, false, false, qin,  W,            Q,  b,          Lq, Dm, Dm, Dm, Dm, Dm, 0, 0, 0, 1, 1.0f);
    gemm(true, false, false, kvin, W + Dm * Dm,  Kb, b + Dm,     Lk, Dm, Dm, Dm, Dm, Dm, 0, 0, 0, 1, 1.0f);
    gemm(true, false, false, kvin, W + 2*Dm*Dm,  Vb, b + 2*Dm,   Lk, Dm, Dm, Dm, Dm, Dm, 0, 0, 0, 1, 1.0f);
    // scores: S[h] = scale * Q_h K_h^T   (batched over heads)
    gemm(true, false, false, Q, Kb, S, nullptr,
         Lq, Lk, HDm, Dm, Dm, Lk, HDm, HDm, (long)Lq * Lk, Hh, scale);
    softmax_kernel<<<Hh * Lq, 256>>>(S, Lk);
    // AV: O_h = S_h V_h
    gemm(false, false, false, S, Vb, O, nullptr,
         Lq, HDm, Lk, Lk, Dm, Dm, (long)Lq * Lk, HDm, HDm, Hh, 1.0f);
    // output projection (+ optional accumulate into outp)
    gemm(true, addc, false, O, Wo, outp, bo, Lq, Dm, Dm, Dm, Dm, Dm, 0, 0, 0, 1, 1.0f);
}

// ---------------- entry point ----------------
extern "C" void kernel_launch(void* const* d_in, const int* in_sizes, int n_in,
                              void* d_out, int out_size)
{
    const float* sp_in = (const float*)d_in[0];
    const float* su_in = (const float*)d_in[1];
    const float* ep    = (const float*)d_in[2];
    const int* ind_pair = (const int*)d_in[3];
    const int* ind_e2e  = (const int*)d_in[4];
    const int* ind_n2e  = (const int*)d_in[5];
    const float* Win  = (const float*)d_in[6];
    const float* bin  = (const float*)d_in[7];
    const float* Wout = (const float*)d_in[8];
    const float* bout = (const float*)d_in[9];
    const float* feW1 = (const float*)d_in[10];
    const float* feb1 = (const float*)d_in[11];
    const float* feW2 = (const float*)d_in[12];
    const float* feb2 = (const float*)d_in[13];
    const float* fnW1 = (const float*)d_in[14];
    const float* fnb1 = (const float*)d_in[15];
    const float* fnW2 = (const float*)d_in[16];
    const float* fnb2 = (const float*)d_in[17];
    const float* lng  = (const float*)d_in[18];
    const float* lnb  = (const float*)d_in[19];
    float* out = (float*)d_out;

    float* sc = nullptr;
    int* pos = nullptr;
    cudaGetSymbolAddress((void**)&sc, g_scratch);
    cudaGetSymbolAddress((void**)&pos, g_pos);

    float* Q   = sc + 0 * M1;
    float* Kb  = sc + 2 * M1;
    float* Vb  = sc + 6 * M1;
    float* S   = sc + 10 * M1;
    float* O   = sc + 74 * M1;
    float* T1  = sc + 76 * M1;
    float* ACC = sc + 78 * M1;
    float* SP  = sc + 80 * M1;
    float* SU  = sc + 82 * M1;
    float* E2E = sc + 83 * M1;
    float* N2E = sc + 87 * M1;
    float* UPB = sc + 91 * M1;
    float* UUB = sc + 93 * M1;
    float* HID = sc + 94 * M1;

    float* out_uu = out;                        // [NN, D]
    float* out_up = out + (long)NNn * Dm;       // [ES, D]

    // ---- self-attention blocks + norm1 / norm1_unary ----
    run_mha(0, sp_in, ESn, sp_in, ESn, T1, false, Win, bin, Wout, bout, Q, Kb, Vb, S, O);
    add_ln_kernel<<<ESn, 256>>>(sp_in, T1, lng + 0 * Dm, lnb + 0 * Dm, SP);

    run_mha(1, su_in, NNn, su_in, NNn, T1, false, Win, bin, Wout, bout, Q, Kb, Vb, S, O);
    add_ln_kernel<<<NNn, 256>>>(su_in, T1, lng + 3 * Dm, lnb + 3 * Dm, SU);

    // ---- scatter sp into entire_pair (as inverse-index map), then gather ----
    init_pos_kernel<<<EPn / 256, 256>>>(pos);
    scatter_pos_kernel<<<ESn / 256, 256>>>(ind_pair, pos);
    gather_rows_kernel<<<(Kn * (Dm / 4)) / 256, 256>>>(ind_e2e, pos, SP, ep, E2E);
    gather_rows_kernel<<<(Kn * (Dm / 4)) / 256, 256>>>(ind_n2e, pos, SP, ep, N2E);

    // ---- edge update: e2e + e2n attention, norm2, FFN, norm3 ----
    run_mha(2, SP, ESn, E2E, Kn,  ACC, false, Win, bin, Wout, bout, Q, Kb, Vb, S, O);
    run_mha(3, SP, ESn, SU,  NNn, ACC, true,  Win, bin, Wout, bout, Q, Kb, Vb, S, O);
    add_ln_kernel<<<ESn, 256>>>(SP, ACC, lng + 1 * Dm, lnb + 1 * Dm, UPB);
    gemm(true, false, true,  UPB, feW1, HID, feb1, ESn, FFm, Dm,  Dm,  Dm,  FFm, 0, 0, 0, 1, 1.0f);
    gemm(true, false, false, HID, feW2, T1,  feb2, ESn, Dm,  FFm, FFm, FFm, Dm,  0, 0, 0, 1, 1.0f);
    add_ln_kernel<<<ESn, 256>>>(UPB, T1, lng + 2 * Dm, lnb + 2 * Dm, out_up);

    // ---- node update: n2e + n2n attention, norm2, FFN, norm3 (shared LN params) ----
    run_mha(4, SU, NNn, N2E, Kn,  ACC, false, Win, bin, Wout, bout, Q, Kb, Vb, S, O);
    run_mha(5, SU, NNn, SU,  NNn, ACC, true,  Win, bin, Wout, bout, Q, Kb, Vb, S, O);
    add_ln_kernel<<<NNn, 256>>>(SU, ACC, lng + 1 * Dm, lnb + 1 * Dm, UUB);
    gemm(true, false, true,  UUB, fnW1, HID, fnb1, NNn, FFm, Dm,  Dm,  Dm,  FFm, 0, 0, 0, 1, 1.0f);
    gemm(true, false, false, HID, fnW2, T1,  fnb2, NNn, Dm,  FFm, FFm, FFm, Dm,  0, 0, 0, 1, 1.0f);
    add_ln_kernel<<<NNn, 256>>>(UUB, T1, lng + 2 * Dm, lnb + 2 * Dm, out_uu);
}

// round 16
// speedup vs baseline: 1.6063x; 1.6063x over previous
#include <cuda_runtime.h>
#include <math.h>

// ---------------- problem constants ----------------
#define Dm   1024
#define Hh   8
#define HDm  128
#define FFm  1024
#define ESn  2048
#define NNn  1024
#define EPn  16384
#define Kn   4096
#define LNEPS 1e-5f

// ---------------- scratch (static device globals; no allocation) ----------------
// layout in floats (M1 = 1M floats):
//  Q:0(2M) K:2(4M) V:6(4M) S:10(64M) O:74(2M) T1:76(2M) ACC:78(2M)
//  SP:80(2M) SU:82(1M) E2E:83(4M) N2E:87(4M) UPB:91(2M) UUB:93(1M) HID:94(2M)  total 96M
#define M1 1048576LL
__device__ float g_scratch[96 * 1048576];
__device__ int   g_pos[EPn];

// ---------------- block reductions ----------------
__device__ __forceinline__ float blockReduceSum(float v) {
    __shared__ float sh[32];
    __shared__ float tot;
    int lane = threadIdx.x & 31, wid = threadIdx.x >> 5;
    #pragma unroll
    for (int o = 16; o > 0; o >>= 1) v += __shfl_down_sync(0xffffffffu, v, o);
    if (lane == 0) sh[wid] = v;
    __syncthreads();
    v = (threadIdx.x < (blockDim.x >> 5)) ? sh[threadIdx.x] : 0.f;
    if (wid == 0) {
        #pragma unroll
        for (int o = 16; o > 0; o >>= 1) v += __shfl_down_sync(0xffffffffu, v, o);
        if (lane == 0) tot = v;
    }
    __syncthreads();
    return tot;
}

__device__ __forceinline__ float blockReduceMax(float v) {
    __shared__ float sh[32];
    __shared__ float tot;
    int lane = threadIdx.x & 31, wid = threadIdx.x >> 5;
    #pragma unroll
    for (int o = 16; o > 0; o >>= 1) v = fmaxf(v, __shfl_down_sync(0xffffffffu, v, o));
    if (lane == 0) sh[wid] = v;
    __syncthreads();
    v = (threadIdx.x < (blockDim.x >> 5)) ? sh[threadIdx.x] : -1e30f;
    if (wid == 0) {
        #pragma unroll
        for (int o = 16; o > 0; o >>= 1) v = fmaxf(v, __shfl_down_sync(0xffffffffu, v, o));
        if (lane == 0) tot = v;
    }
    __syncthreads();
    return tot;
}

// ---------------- generic batched tiled SGEMM ----------------
// C[M,N] = alpha * A(M,Kd) x op(B) (+ bias[n]) (+ C) (ReLU)
// TRANSB=true : B is [N,Kd] row-major (dot of rows)   -> X @ W^T
// TRANSB=false: B is [Kd,N] row-major                  -> S @ V
template<int BM, int BN, int TM, int TN, bool TRANSB, bool ADDC, bool RELU>
__global__ void __launch_bounds__(256)
gemm_kernel(const float* __restrict__ A, const float* __restrict__ B,
            float* __restrict__ C, const float* __restrict__ bias,
            int M, int N, int Kd, int lda, int ldb, int ldc,
            long sA, long sB, long sC, float alpha)
{
    constexpr int BK = 16;
    __shared__ float As[BK][BM];
    __shared__ float Bs[BK][BN];
    A += (long)blockIdx.z * sA;
    B += (long)blockIdx.z * sB;
    C += (long)blockIdx.z * sC;
    const int bm = blockIdx.y * BM;
    const int bn = blockIdx.x * BN;
    const int tid = threadIdx.x;
    constexpr int TCOLS = BN / TN;
    const int tx = tid % TCOLS;
    const int ty = tid / TCOLS;

    float acc[TM][TN];
    #pragma unroll
    for (int i = 0; i < TM; i++)
        #pragma unroll
        for (int j = 0; j < TN; j++) acc[i][j] = 0.f;

    for (int k0 = 0; k0 < Kd; k0 += BK) {
        // A tile -> As[k][m] (transposed on load)
        constexpr int LA = (BM * BK / 4) / 256;
        #pragma unroll
        for (int i = 0; i < LA; i++) {
            int idx = tid + i * 256;
            int row = idx >> 2;            // BK/4 = 4 float4 per row
            int c   = (idx & 3) << 2;
            const float4 v = *(const float4*)(A + (long)(bm + row) * lda + k0 + c);
            As[c + 0][row] = v.x; As[c + 1][row] = v.y;
            As[c + 2][row] = v.z; As[c + 3][row] = v.w;
        }
        if (TRANSB) {
            constexpr int LB = (BN * BK / 4) / 256;
            #pragma unroll
            for (int i = 0; i < LB; i++) {
                int idx = tid + i * 256;
                int row = idx >> 2;
                int c   = (idx & 3) << 2;
                const float4 v = *(const float4*)(B + (long)(bn + row) * ldb + k0 + c);
                Bs[c + 0][row] = v.x; Bs[c + 1][row] = v.y;
                Bs[c + 2][row] = v.z; Bs[c + 3][row] = v.w;
            }
        } else {
            constexpr int LB = (BK * BN / 4) / 256;
            constexpr int C4 = BN / 4;
            #pragma unroll
            for (int i = 0; i < LB; i++) {
                int idx = tid + i * 256;
                int kr  = idx / C4;
                int c   = (idx % C4) << 2;
                *(float4*)(&Bs[kr][c]) =
                    *(const float4*)(B + (long)(k0 + kr) * ldb + bn + c);
            }
        }
        __syncthreads();
        #pragma unroll
        for (int k = 0; k < BK; k++) {
            float af[TM], bf[TN];
            #pragma unroll
            for (int i = 0; i < TM; i += 4)
                *(float4*)(af + i) = *(const float4*)(&As[k][ty * TM + i]);
            #pragma unroll
            for (int j = 0; j < TN; j += 4)
                *(float4*)(bf + j) = *(const float4*)(&Bs[k][tx * TN + j]);
            #pragma unroll
            for (int i = 0; i < TM; i++)
                #pragma unroll
                for (int j = 0; j < TN; j++)
                    acc[i][j] = fmaf(af[i], bf[j], acc[i][j]);
        }
        __syncthreads();
    }

    #pragma unroll
    for (int i = 0; i < TM; i++) {
        const long m = bm + ty * TM + i;
        #pragma unroll
        for (int j = 0; j < TN; j += 4) {
            const int n = bn + tx * TN + j;
            float4 r;
            r.x = acc[i][j + 0] * alpha; r.y = acc[i][j + 1] * alpha;
            r.z = acc[i][j + 2] * alpha; r.w = acc[i][j + 3] * alpha;
            if (bias) {
                const float4 bb = *(const float4*)(bias + n);
                r.x += bb.x; r.y += bb.y; r.z += bb.z; r.w += bb.w;
            }
            if (ADDC) {
                const float4 c0 = *(const float4*)(C + m * ldc + n);
                r.x += c0.x; r.y += c0.y; r.z += c0.z; r.w += c0.w;
            }
            if (RELU) {
                r.x = fmaxf(r.x, 0.f); r.y = fmaxf(r.y, 0.f);
                r.z = fmaxf(r.z, 0.f); r.w = fmaxf(r.w, 0.f);
            }
            *(float4*)(C + m * ldc + n) = r;
        }
    }
}

// ---------------- softmax over last dim (one block per row) ----------------
__global__ void softmax_kernel(float* __restrict__ S, int Lk) {
    float* p = S + (long)blockIdx.x * Lk;
    const int tid = threadIdx.x;
    float m = -1e30f;
    for (int i = tid; i < Lk; i += 256) m = fmaxf(m, p[i]);
    m = blockReduceMax(m);
    float s = 0.f;
    for (int i = tid; i < Lk; i += 256) {
        float e = expf(p[i] - m);
        p[i] = e;
        s += e;
    }
    s = blockReduceSum(s);
    const float inv = 1.0f / s;
    for (int i = tid; i < Lk; i += 256) p[i] *= inv;
}

// ---------------- fused residual add + LayerNorm (one block per row) ----------------
__global__ void add_ln_kernel(const float* __restrict__ a, const float* __restrict__ b,
                              const float* __restrict__ g, const float* __restrict__ be,
                              float* __restrict__ out) {
    const int row = blockIdx.x;
    const int tid = threadIdx.x;
    const float* pa = a + (long)row * Dm;
    const float* pb = b + (long)row * Dm;
    float v[4];
    float s = 0.f;
    #pragma unroll
    for (int i = 0; i < 4; i++) {
        int c = tid + i * 256;
        v[i] = pa[c] + pb[c];
        s += v[i];
    }
    s = blockReduceSum(s);
    const float mu = s * (1.0f / Dm);
    float q = 0.f;
    #pragma unroll
    for (int i = 0; i < 4; i++) { float d = v[i] - mu; q += d * d; }
    q = blockReduceSum(q);
    const float rstd = rsqrtf(q * (1.0f / Dm) + LNEPS);
    #pragma unroll
    for (int i = 0; i < 4; i++) {
        int c = tid + i * 256;
        out[(long)row * Dm + c] = (v[i] - mu) * rstd * g[c] + be[c];
    }
}

// ---------------- scatter/gather plumbing ----------------
__global__ void init_pos_kernel(int* pos) {
    int i = blockIdx.x * 256 + threadIdx.x;
    pos[i] = -1;
}
__global__ void scatter_pos_kernel(const int* __restrict__ ind, int* pos) {
    int i = blockIdx.x * 256 + threadIdx.x;
    pos[ind[i]] = i;
}
// out[j,:] = pos[ind[j]]>=0 ? sp[pos] : entire_pair[ind[j]]
__global__ void gather_rows_kernel(const int* __restrict__ ind, const int* __restrict__ pos,
                                   const float* __restrict__ sp, const float* __restrict__ ep,
                                   float* __restrict__ out) {
    long t = (long)blockIdx.x * 256 + threadIdx.x; // one float4 per thread
    int j = (int)(t >> 8);                         // D/4 = 256 float4 per row
    int c = (int)(t & 255) << 2;
    int idx = ind[j];
    int p = pos[idx];
    const float* src = (p >= 0) ? (sp + (long)p * Dm) : (ep + (long)idx * Dm);
    *(float4*)(out + (long)j * Dm + c) = *(const float4*)(src + c);
}

// ---------------- host-side GEMM dispatch ----------------
template<bool TB, bool AC, bool RL>
static void gemm_t(const float* A, const float* B, float* C, const float* bias,
                   int M, int N, int Kd, int lda, int ldb, int ldc,
                   long sA, long sB, long sC, int batch, float alpha)
{
    bool big = (M % 128 == 0) && (N % 128 == 0) &&
               ((long)(M / 128) * (N / 128) * batch >= 160);
    if (big) {
        dim3 g(N / 128, M / 128, batch);
        gemm_kernel<128, 128, 8, 8, TB, AC, RL><<<g, 256>>>(
            A, B, C, bias, M, N, Kd, lda, ldb, ldc, sA, sB, sC, alpha);
    } else {
        dim3 g(N / 64, M / 64, batch);
        gemm_kernel<64, 64, 4, 4, TB, AC, RL><<<g, 256>>>(
            A, B, C, bias, M, N, Kd, lda, ldb, ldc, sA, sB, sC, alpha);
    }
}

static void gemm(bool transb, bool addc, bool relu,
                 const float* A, const float* B, float* C, const float* bias,
                 int M, int N, int Kd, int lda, int ldb, int ldc,
                 long sA, long sB, long sC, int batch, float alpha)
{
    if (transb) {
        if (addc) {
            if (relu) gemm_t<true, true, true>(A,B,C,bias,M,N,Kd,lda,ldb,ldc,sA,sB,sC,batch,alpha);
            else      gemm_t<true, true, false>(A,B,C,bias,M,N,Kd,lda,ldb,ldc,sA,sB,sC,batch,alpha);
        } else {
            if (relu) gemm_t<true, false, true>(A,B,C,bias,M,N,Kd,lda,ldb,ldc,sA,sB,sC,batch,alpha);
            else      gemm_t<true, false, false>(A,B,C,bias,M,N,Kd,lda,ldb,ldc,sA,sB,sC,batch,alpha);
        }
    } else {
        if (addc) {
            if (relu) gemm_t<false, true, true>(A,B,C,bias,M,N,Kd,lda,ldb,ldc,sA,sB,sC,batch,alpha);
            else      gemm_t<false, true, false>(A,B,C,bias,M,N,Kd,lda,ldb,ldc,sA,sB,sC,batch,alpha);
        } else {
            if (relu) gemm_t<false, false, true>(A,B,C,bias,M,N,Kd,lda,ldb,ldc,sA,sB,sC,batch,alpha);
            else      gemm_t<false, false, false>(A,B,C,bias,M,N,Kd,lda,ldb,ldc,sA,sB,sC,batch,alpha);
        }
    }
}

// ---------------- MHA driver ----------------
// outp[Lq, D] (+=) = MHA_i(q_in, kv_in)
static void run_mha(int i, const float* qin, int Lq, const float* kvin, int Lk,
                    float* outp, bool addc,
                    const float* Win, const float* bin,
                    const float* Wout, const float* bout,
                    float* Q, float* Kb, float* Vb, float* S, float* O)
{
    const float* W  = Win + (size_t)i * 3 * Dm * Dm;
    const float* b  = bin + (size_t)i * 3 * Dm;
    const float* Wo = Wout + (size_t)i * Dm * Dm;
    const float* bo = bout + (size_t)i * Dm;
    const float scale = 0.08838834764831845f;  // 1/sqrt(128)

    // projections: X @ W^T + b
    gemm(true, false, false, qin,  W,            Q,  b,          Lq, Dm, Dm, Dm, Dm, Dm, 0, 0, 0, 1, 1.0f);
    gemm(true, false, false, kvin, W + Dm * Dm,  Kb, b + Dm,     Lk, Dm, Dm, Dm, Dm, Dm, 0, 0, 0, 1, 1.0f);
    gemm(true, false, false, kvin, W + 2*Dm*Dm,  Vb, b + 2*Dm,   Lk, Dm, Dm, Dm, Dm, Dm, 0, 0, 0, 1, 1.0f);
    // scores: S[h] = scale * Q_h K_h^T   (batched over heads)
    gemm(true, false, false, Q, Kb, S, nullptr,
         Lq, Lk, HDm, Dm, Dm, Lk, HDm, HDm, (long)Lq * Lk, Hh, scale);
    softmax_kernel<<<Hh * Lq, 256>>>(S, Lk);
    // AV: O_h = S_h V_h
    gemm(false, false, false, S, Vb, O, nullptr,
         Lq, HDm, Lk, Lk, Dm, Dm, (long)Lq * Lk, HDm, HDm, Hh, 1.0f);
    // output projection (+ optional accumulate into outp)
    gemm(true, addc, false, O, Wo, outp, bo, Lq, Dm, Dm, Dm, Dm, Dm, 0, 0, 0, 1, 1.0f);
}

// ---------------- entry point ----------------
extern "C" void kernel_launch(void* const* d_in, const int* in_sizes, int n_in,
                              void* d_out, int out_size)
{
    const float* sp_in = (const float*)d_in[0];
    const float* su_in = (const float*)d_in[1];
    const float* ep    = (const float*)d_in[2];
    const int* ind_pair = (const int*)d_in[3];
    const int* ind_e2e  = (const int*)d_in[4];
    const int* ind_n2e  = (const int*)d_in[5];
    const float* Win  = (const float*)d_in[6];
    const float* bin  = (const float*)d_in[7];
    const float* Wout = (const float*)d_in[8];
    const float* bout = (const float*)d_in[9];
    const float* feW1 = (const float*)d_in[10];
    const float* feb1 = (const float*)d_in[11];
    const float* feW2 = (const float*)d_in[12];
    const float* feb2 = (const float*)d_in[13];
    const float* fnW1 = (const float*)d_in[14];
    const float* fnb1 = (const float*)d_in[15];
    const float* fnW2 = (const float*)d_in[16];
    const float* fnb2 = (const float*)d_in[17];
    const float* lng  = (const float*)d_in[18];
    const float* lnb  = (const float*)d_in[19];
    float* out = (float*)d_out;

    float* sc = nullptr;
    int* pos = nullptr;
    cudaGetSymbolAddress((void**)&sc, g_scratch);
    cudaGetSymbolAddress((void**)&pos, g_pos);

    float* Q   = sc + 0 * M1;
    float* Kb  = sc + 2 * M1;
    float* Vb  = sc + 6 * M1;
    float* S   = sc + 10 * M1;
    float* O   = sc + 74 * M1;
    float* T1  = sc + 76 * M1;
    float* ACC = sc + 78 * M1;
    float* SP  = sc + 80 * M1;
    float* SU  = sc + 82 * M1;
    float* E2E = sc + 83 * M1;
    float* N2E = sc + 87 * M1;
    float* UPB = sc + 91 * M1;
    float* UUB = sc + 93 * M1;
    float* HID = sc + 94 * M1;

    float* out_uu = out;                        // [NN, D]
    float* out_up = out + (long)NNn * Dm;       // [ES, D]

    // ---- self-attention blocks + norm1 / norm1_unary ----
    run_mha(0, sp_in, ESn, sp_in, ESn, T1, false, Win, bin, Wout, bout, Q, Kb, Vb, S, O);
    add_ln_kernel<<<ESn, 256>>>(sp_in, T1, lng + 0 * Dm, lnb + 0 * Dm, SP);

    run_mha(1, su_in, NNn, su_in, NNn, T1, false, Win, bin, Wout, bout, Q, Kb, Vb, S, O);
    add_ln_kernel<<<NNn, 256>>>(su_in, T1, lng + 3 * Dm, lnb + 3 * Dm, SU);

    // ---- scatter sp into entire_pair (as inverse-index map), then gather ----
    init_pos_kernel<<<EPn / 256, 256>>>(pos);
    scatter_pos_kernel<<<ESn / 256, 256>>>(ind_pair, pos);
    gather_rows_kernel<<<(Kn * (Dm / 4)) / 256, 256>>>(ind_e2e, pos, SP, ep, E2E);
    gather_rows_kernel<<<(Kn * (Dm / 4)) / 256, 256>>>(ind_n2e, pos, SP, ep, N2E);

    // ---- edge update: e2e + e2n attention, norm2, FFN, norm3 ----
    run_mha(2, SP, ESn, E2E, Kn,  ACC, false, Win, bin, Wout, bout, Q, Kb, Vb, S, O);
    run_mha(3, SP, ESn, SU,  NNn, ACC, true,  Win, bin, Wout, bout, Q, Kb, Vb, S, O);
    add_ln_kernel<<<ESn, 256>>>(SP, ACC, lng + 1 * Dm, lnb + 1 * Dm, UPB);
    gemm(true, false, true,  UPB, feW1, HID, feb1, ESn, FFm, Dm,  Dm,  Dm,  FFm, 0, 0, 0, 1, 1.0f);
    gemm(true, false, false, HID, feW2, T1,  feb2, ESn, Dm,  FFm, FFm, FFm, Dm,  0, 0, 0, 1, 1.0f);
    add_ln_kernel<<<ESn, 256>>>(UPB, T1, lng + 2 * Dm, lnb + 2 * Dm, out_up);

    // ---- node update: n2e + n2n attention, norm2, FFN, norm3 (shared LN params) ----
    run_mha(4, SU, NNn, N2E, Kn,  ACC, false, Win, bin, Wout, bout, Q, Kb, Vb, S, O);
    run_mha(5, SU, NNn, SU,  NNn, ACC, true,  Win, bin, Wout, bout, Q, Kb, Vb, S, O);
    add_ln_kernel<<<NNn, 256>>>(SU, ACC, lng + 1 * Dm, lnb + 1 * Dm, UUB);
    gemm(true, false, true,  UUB, fnW1, HID, fnb1, NNn, FFm, Dm,  Dm,  Dm,  FFm, 0, 0, 0, 1, 1.0f);
    gemm(true, false, false, HID, fnW2, T1,  fnb2, NNn, Dm,  FFm, FFm, FFm, Dm,  0, 0, 0, 1, 1.0f);
    add_ln_kernel<<<NNn, 256>>>(UUB, T1, lng + 2 * Dm, lnb + 2 * Dm, out_uu);
}